// round 14
// baseline (speedup 1.0000x reference)
#include <cuda_runtime.h>
#include <cuda_bf16.h>
#include <stdint.h>
#include <math.h>

#define BB 2
#define LL 2048
#define DM 512
#define DI 1024
#define DS 16
#define NTOK (BB*LL)   // 4096
#define TCHUNK 32
#define CH 16

typedef unsigned short bf16raw;

static __device__ __forceinline__ bf16raw f2b(float x){
    __nv_bfloat16 h = __float2bfloat16_rn(x);
    return *reinterpret_cast<bf16raw*>(&h);
}
static __device__ __forceinline__ float b2f(bf16raw v){
    __nv_bfloat16 h = *reinterpret_cast<__nv_bfloat16*>(&v);
    return __bfloat162float(h);
}
static __device__ __forceinline__ void cp16(void* dst, const void* src){
    unsigned sa = (unsigned)__cvta_generic_to_shared(dst);
    asm volatile("cp.async.cg.shared.global [%0], [%1], 16;" :: "r"(sa), "l"(src));
}

// ---------------- scratch -------------------------------------------------
__device__ bf16raw g_xz_bf[2][NTOK*2*DI];    // in-proj out (xi|z), bf16
__device__ bf16raw g_xn_bf[NTOK*DM];
__device__ bf16raw g_xi_bf[2][NTOK*DI];      // conv+silu out bf16 (GEMM2 A + scan)
__device__ bf16raw g_ycat_bf[NTOK*2*DI];
__device__ bf16raw g_wcomb[2*DI*DM];         // folded Wcat@Wproj [2048][512]
__device__ float   g_part2[4][NTOK*64];      // GEMM2 split-K partials (summed in scan)
// bf16 weights
__device__ bf16raw g_w_in[2][DM*2*DI];
__device__ bf16raw g_w_xp[2][DI*64];
__device__ bf16raw g_w_cat[2*DI*DM];
__device__ bf16raw g_w_pj[DM*DM];

// ---------------- merged layernorm + weight conversion ---------------------
struct CvtArgs { const float* s[7]; bf16raw* d[7]; int off[8]; };

__global__ __launch_bounds__(128) void ln_cvt_kernel(
    CvtArgs a, int total4,
    const float* __restrict__ x,
    const float* __restrict__ g,
    const float* __restrict__ b)
{
    int tid = threadIdx.x;
    if (blockIdx.x < NTOK){
        int row = blockIdx.x;
        const float4* xr = (const float4*)(x + (long)row*DM);
        float4 v = xr[tid];
        float s = v.x+v.y+v.z+v.w;
        float q = v.x*v.x+v.y*v.y+v.z*v.z+v.w*v.w;
        #pragma unroll
        for (int o=16;o>0;o>>=1){
            s += __shfl_xor_sync(0xffffffffu, s, o);
            q += __shfl_xor_sync(0xffffffffu, q, o);
        }
        __shared__ float ss[4], sq[4];
        int wid = tid>>5, lane = tid&31;
        if (lane==0){ ss[wid]=s; sq[wid]=q; }
        __syncthreads();
        float S = ss[0]+ss[1]+ss[2]+ss[3];
        float Q = sq[0]+sq[1]+sq[2]+sq[3];
        float mu = S*(1.0f/DM);
        float var = Q*(1.0f/DM) - mu*mu;
        float rs = rsqrtf(var + 1e-5f);
        float4 gv = ((const float4*)g)[tid];
        float4 bv = ((const float4*)b)[tid];
        ushort4 o;
        o.x = f2b((v.x-mu)*rs*gv.x + bv.x);
        o.y = f2b((v.y-mu)*rs*gv.y + bv.y);
        o.z = f2b((v.z-mu)*rs*gv.z + bv.z);
        o.w = f2b((v.w-mu)*rs*gv.w + bv.w);
        ((ushort4*)(g_xn_bf + (long)row*DM))[tid] = o;
    } else {
        int i = (blockIdx.x - NTOK)*128 + tid;   // float4 index
        if (i >= total4) return;
        int seg = 0;
        while (i >= a.off[seg+1]) seg++;
        int j = (i - a.off[seg])*4;
        float4 v = *(const float4*)(a.s[seg] + j);
        bf16raw* d = a.d[seg] + j;
        d[0]=f2b(v.x); d[1]=f2b(v.y); d[2]=f2b(v.z); d[3]=f2b(v.w);
    }
}

// ---------------- bf16 tensor-core GEMM -------------------------------------
// 128 threads, 2x2 warp grid, warp tile (MT/2)x64, 3-stage cp.async pipeline.
template<int BK, int MT, int ZS>
__global__ __launch_bounds__(128, 2) void hgemm(
    const bf16raw* __restrict__ Ag, long sA, int lda,
    const bf16raw* __restrict__ Bg, long sB, int ldb,
    float* __restrict__ Cg, long sC, int ldc,
    bf16raw* __restrict__ Obg, long sO,
    int N, int K,
    const float* __restrict__ biasg, long sbias,
    const float* __restrict__ res, int ldres,
    int epi,
    long sA2, long sB2, long sC2)
{
    const int NST = 3;
    int zo, zi;
    if (ZS){ zo = blockIdx.z>>1; zi = blockIdx.z&1; }
    else   { zo = blockIdx.z;    zi = 0; }
    const bf16raw* A = Ag + sA*zo + (ZS ? sA2*zi : 0);
    const bf16raw* B = Bg + sB*zo + (ZS ? sB2*zi : 0);
    float* C   = Cg  ? Cg  + sC*zo + (ZS ? sC2*zi : 0) : nullptr;
    bf16raw* Ob = Obg ? Obg + sO*zo : nullptr;
    const float* bias = biasg ? biasg + sbias*zo : nullptr;

    extern __shared__ __align__(16) bf16raw sdyn[];
    const int ABUF = MT*(BK+8);
    const int BBUF = BK*128;
    bf16raw* As = sdyn;
    bf16raw* Bs = sdyn + NST*ABUF;

    int tid = threadIdx.x;
    int lane = tid & 31, wid = tid >> 5;
    int warp_m = wid & 1, warp_n = wid >> 1;
    int bm = blockIdx.y*MT, bn = blockIdx.x*128;

    const int MTI = MT/32;
    float acc[MTI][8][4];
    #pragma unroll
    for (int a=0;a<MTI;a++) for (int b2=0;b2<8;b2++) for (int c=0;c<4;c++) acc[a][b2][c]=0.f;

    int KT = K / BK;
    const int CPR = BK/8;

    auto loadTile = [&](int kt, int buf){
        int k0 = kt*BK;
        #pragma unroll
        for (int i=0;i<MT*BK/1024;i++){
            int q = tid + i*128;
            int r = q / CPR, c = q % CPR;
            const bf16raw* src = A + (long)(bm+r)*lda + k0 + c*8;
            unsigned sa = (unsigned)__cvta_generic_to_shared(&As[buf*ABUF + r*(BK+8) + c*8]);
            asm volatile("cp.async.cg.shared.global [%0], [%1], 16;\n" :: "r"(sa), "l"(src));
        }
        #pragma unroll
        for (int i=0;i<BK/8;i++){
            int q = tid + i*128;
            int r = q>>4, c = q&15;
            int gcol = bn + c*8;
            const bf16raw* src = B + (long)(k0+r)*ldb + gcol;
            unsigned sa = (unsigned)__cvta_generic_to_shared(&Bs[buf*BBUF + r*128 + ((c ^ (r&7))*8)]);
            int sz = (gcol < N) ? 16 : 0;
            asm volatile("cp.async.cg.shared.global [%0], [%1], 16, %2;\n" :: "r"(sa), "l"(src), "r"(sz));
        }
    };

    #pragma unroll
    for (int p=0; p<NST-1; p++){
        loadTile(p, p);
        asm volatile("cp.async.commit_group;\n" ::: "memory");
    }

    for (int kt=0; kt<KT; kt++){
        asm volatile("cp.async.wait_group %0;\n" :: "n"(NST-2) : "memory");
        __syncthreads();
        int buf = kt % NST;

        #pragma unroll
        for (int ks=0; ks<BK/16; ks++){
            unsigned af[MTI][4];
            #pragma unroll
            for (int mt=0; mt<MTI; mt++){
                int row = warp_m*(MT/2) + mt*16 + (lane&15);
                int chunk = ks*2 + (lane>>4);
                unsigned addr = (unsigned)__cvta_generic_to_shared(&As[buf*ABUF + row*(BK+8) + chunk*8]);
                asm volatile("ldmatrix.sync.aligned.m8n8.x4.shared.b16 {%0,%1,%2,%3}, [%4];"
                    : "=r"(af[mt][0]),"=r"(af[mt][1]),"=r"(af[mt][2]),"=r"(af[mt][3]) : "r"(addr));
            }
            unsigned bfm[8][2];
            #pragma unroll
            for (int jn=0; jn<4; jn++){
                int row = ks*16 + (lane&15);
                int c = warp_n*8 + jn*2 + (lane>>4);
                unsigned addr = (unsigned)__cvta_generic_to_shared(&Bs[buf*BBUF + row*128 + ((c ^ (row&7))*8)]);
                unsigned r0,r1,r2,r3;
                asm volatile("ldmatrix.sync.aligned.m8n8.x4.trans.shared.b16 {%0,%1,%2,%3}, [%4];"
                    : "=r"(r0),"=r"(r1),"=r"(r2),"=r"(r3) : "r"(addr));
                bfm[jn*2][0]=r0;   bfm[jn*2][1]=r1;
                bfm[jn*2+1][0]=r2; bfm[jn*2+1][1]=r3;
            }
            #pragma unroll
            for (int mt=0; mt<MTI; mt++)
                #pragma unroll
                for (int nt=0; nt<8; nt++){
                    asm volatile("mma.sync.aligned.m16n8k16.row.col.f32.bf16.bf16.f32 "
                        "{%0,%1,%2,%3}, {%4,%5,%6,%7}, {%8,%9}, {%0,%1,%2,%3};"
                        : "+f"(acc[mt][nt][0]),"+f"(acc[mt][nt][1]),
                          "+f"(acc[mt][nt][2]),"+f"(acc[mt][nt][3])
                        : "r"(af[mt][0]),"r"(af[mt][1]),"r"(af[mt][2]),"r"(af[mt][3]),
                          "r"(bfm[nt][0]),"r"(bfm[nt][1]));
                }
        }

        int nl = kt + NST - 1;
        if (nl < KT){
            loadTile(nl, nl % NST);
            asm volatile("cp.async.commit_group;\n" ::: "memory");
        } else {
            asm volatile("cp.async.commit_group;\n" ::: "memory");
        }
    }

    #pragma unroll
    for (int mt=0; mt<MTI; mt++){
        #pragma unroll
        for (int i2=0; i2<2; i2++){
            long r = bm + warp_m*(MT/2) + mt*16 + (lane>>2) + i2*8;
            #pragma unroll
            for (int nt=0; nt<8; nt++){
                int cbase = bn + warp_n*64 + nt*8 + (lane&3)*2;
                #pragma unroll
                for (int j=0; j<2; j++){
                    int c = cbase + j;
                    if (c >= N) continue;
                    float v = acc[mt][nt][i2*2+j];
                    if (epi==3){ v += bias[c] + res[r*ldres + c]; }
                    if (C)  C[r*ldc + c] = v;
                    if (Ob) Ob[r*ldc + c] = f2b(v);
                }
            }
        }
    }
}

// ---------------- depthwise conv + SiLU: vectorized x4, one token/block ----
__global__ __launch_bounds__(256) void conv_kernel(
    const float* __restrict__ wf, const float* __restrict__ biasf,
    const float* __restrict__ wb, const float* __restrict__ biasb)
{
    int dir = blockIdx.z;
    const float* w    = dir ? wb : wf;
    const float* bias = dir ? biasb : biasf;
    int tok = blockIdx.x;
    int t = tok & (LL-1);
    int b = tok >> 11;
    int d4 = threadIdx.x * 4;
    const bf16raw* xz = g_xz_bf[dir];

    float4 wv0 = ((const float4*)w)[d4+0];
    float4 wv1 = ((const float4*)w)[d4+1];
    float4 wv2 = ((const float4*)w)[d4+2];
    float4 wv3 = ((const float4*)w)[d4+3];
    float4 bv  = ((const float4*)bias)[threadIdx.x];
    float acc0=bv.x, acc1=bv.y, acc2=bv.z, acc3=bv.w;

    #pragma unroll
    for (int j=0;j<4;j++){
        int tt = (dir==0) ? (t-3+j) : (t+3-j);
        if (tt<0 || tt>=LL) continue;
        ushort4 v = *(const ushort4*)(xz + ((long)(b*LL+tt)*2*DI) + d4);
        float wj0 = ((const float*)&wv0)[j];
        float wj1 = ((const float*)&wv1)[j];
        float wj2 = ((const float*)&wv2)[j];
        float wj3 = ((const float*)&wv3)[j];
        acc0 = fmaf(wj0, b2f(v.x), acc0);
        acc1 = fmaf(wj1, b2f(v.y), acc1);
        acc2 = fmaf(wj2, b2f(v.z), acc2);
        acc3 = fmaf(wj3, b2f(v.w), acc3);
    }
    ushort4 o;
    o.x = f2b(acc0 / (1.f + __expf(-acc0)));
    o.y = f2b(acc1 / (1.f + __expf(-acc1)));
    o.z = f2b(acc2 / (1.f + __expf(-acc2)));
    o.w = f2b(acc3 / (1.f + __expf(-acc3)));
    *(ushort4*)(g_xi_bf[dir] + (long)tok*DI + d4) = o;
}

// ---------------- selective scan: fused dt proj + split-K combine ----------
struct ScanSmem {
    float   p0[2][TCHUNK][64];   // GEMM2 partial 0
    float   p1[2][TCHUNK][64];   // GEMM2 partial 1
    float   xd[TCHUNK][64];      // summed xdbl: [0:32) dt-in, [32:48) B, [48:64) C
    bf16raw xi[2][TCHUNK][CH];
    bf16raw z [2][TCHUNK][CH];
    float   dtw[32][CH];
    float   dts[TCHUNK][CH];
    float   dtx[TCHUNK][CH];
    float   dtb[CH];
    float   p [TCHUNK][CH][17];
};

__global__ __launch_bounds__(256) void scan_kernel(
    const float* __restrict__ fA, const float* __restrict__ fD,
    const float* __restrict__ bA, const float* __restrict__ bD,
    const float* __restrict__ fdtw, const float* __restrict__ fdtb,
    const float* __restrict__ bdtw, const float* __restrict__ bdtb)
{
    extern __shared__ char smem_raw[];
    ScanSmem* S = reinterpret_cast<ScanSmem*>(smem_raw);

    int dir = blockIdx.z;
    int b   = blockIdx.y;
    int d0  = blockIdx.x * CH;
    const float* A_log = dir ? bA : fA;
    const float* Dp    = dir ? bD : fD;
    const float* dtwg  = dir ? bdtw : fdtw;
    const float* dtbg  = dir ? bdtb : fdtb;

    int tid  = threadIdx.x;
    int wid  = tid >> 5, lane = tid & 31;
    int half = lane >> 4, n = lane & 15;
    int dl   = wid*2 + half;

    float a    = -expf(A_log[(d0+dl)*DS + n]);
    float Dv_r = Dp[d0 + (tid & 15)];

    #pragma unroll
    for (int i=0;i<2;i++){
        int q = tid + i*256;
        S->dtw[q>>4][q&15] = dtwg[(long)(q>>4)*DI + d0 + (q&15)];
    }
    if (tid < CH) S->dtb[tid] = dtbg[d0 + tid];

    const bf16raw* xip = g_xi_bf[dir];
    const bf16raw* xzp = g_xz_bf[dir];
    const float*   pp0 = g_part2[dir*2+0];
    const float*   pp1 = g_part2[dir*2+1];

    const int NCH = LL / TCHUNK;

    auto loadChunk = [&](int c, int buf){
        #pragma unroll
        for (int i=0;i<2;i++){
            int q = tid + i*256;
            int row = q >> 4, seg = q & 15;
            int trow = (dir==0) ? c*TCHUNK+row : (LL-1) - (c*TCHUNK+row);
            long tok = (long)b*LL + trow;
            cp16(&S->p0[buf][row][seg*4], pp0 + tok*64 + seg*4);
            cp16(&S->p1[buf][row][seg*4], pp1 + tok*64 + seg*4);
        }
        if (tid < 64){
            int row = tid >> 1, seg = tid & 1;
            int trow = (dir==0) ? c*TCHUNK+row : (LL-1) - (c*TCHUNK+row);
            long tok = (long)b*LL + trow;
            cp16(&S->xi[buf][row][seg*8], xip + tok*DI + d0 + seg*8);
        } else if (tid < 128){
            int rem = tid - 64;
            int row = rem >> 1, seg = rem & 1;
            int trow = (dir==0) ? c*TCHUNK+row : (LL-1) - (c*TCHUNK+row);
            long tok = (long)b*LL + trow;
            cp16(&S->z[buf][row][seg*8], xzp + tok*2*DI + DI + d0 + seg*8);
        }
    };

    float h = 0.f;
    loadChunk(0, 0);
    asm volatile("cp.async.commit_group;\n" ::: "memory");

    for (int c=0; c<NCH; c++){
        if (c+1 < NCH) loadChunk(c+1, (c+1)&1);
        asm volatile("cp.async.commit_group;\n" ::: "memory");
        asm volatile("cp.async.wait_group 1;\n" ::: "memory");
        __syncthreads();
        int buf = c & 1;

        // ---- phase A0: split-K combine -> xd ----
        #pragma unroll
        for (int r=0;r<8;r++){
            int q = tid + r*256;
            int s = q >> 6, col = q & 63;
            S->xd[s][col] = S->p0[buf][s][col] + S->p1[buf][s][col];
        }
        __syncthreads();

        // ---- phase A: dt projection + dtx = dt*xi ----
        #pragma unroll
        for (int rep=0; rep<2; rep++){
            int o = tid + rep*256;
            int s = o >> 4, dlo = o & 15;
            float acc = S->dtb[dlo];
            #pragma unroll
            for (int k=0;k<32;k++) acc = fmaf(S->xd[s][k], S->dtw[k][dlo], acc);
            float dtv = (acc > 20.f) ? acc : log1pf(__expf(acc));
            S->dts[s][dlo] = dtv;
            S->dtx[s][dlo] = dtv * b2f(S->xi[buf][s][dlo]);
        }
        __syncthreads();

        // ---- serial recurrence ----
        #pragma unroll
        for (int s=0; s<TCHUNK; s++){
            float dtv = S->dts[s][dl];
            float dtx = S->dtx[s][dl];
            float Bt  = S->xd[s][32+n];
            float Ct  = S->xd[s][48+n];
            float dA  = __expf(dtv * a);
            h = fmaf(dA, h, dtx*Bt);
            S->p[s][dl][n] = h * Ct;
        }
        __syncthreads();

        // ---- reduction + epilogue + store ----
        #pragma unroll
        for (int rep=0; rep<2; rep++){
            int o  = tid + rep*256;
            int s  = o >> 4, dlo = o & 15;
            float sum = 0.f;
            #pragma unroll
            for (int k=0;k<16;k++) sum += S->p[s][dlo][k];
            float xiv = b2f(S->xi[buf][s][dlo]);
            float zv  = b2f(S->z[buf][s][dlo]);
            float yv  = (sum + xiv*Dv_r) * zv / (1.f + __expf(-zv));
            int trow  = (dir==0) ? c*TCHUNK+s : (LL-1) - (c*TCHUNK+s);
            g_ycat_bf[((long)b*LL + trow)*2*DI + dir*DI + d0 + dlo] = f2b(yv);
        }
        __syncthreads();
    }
}

// ---------------- host launcher --------------------------------------------
extern "C" void kernel_launch(void* const* d_in, const int* in_sizes, int n_in,
                              void* d_out, int out_size){
    const float* x      = (const float*)d_in[0];
    const float* ln_g   = (const float*)d_in[1];
    const float* ln_b   = (const float*)d_in[2];
    const float* proj_w = (const float*)d_in[3];
    const float* proj_b = (const float*)d_in[4];
    const float* P[2][9];
    for (int dir=0; dir<2; dir++)
        for (int i=0;i<9;i++)
            P[dir][i] = (const float*)d_in[5 + dir*9 + i];

    float   *p_part2;
    bf16raw *p_xzb,*p_xn,*p_xib,*p_ycat,*p_wcomb;
    bf16raw *w_in,*w_xp,*w_cat,*w_pj;
    cudaGetSymbolAddress((void**)&p_xzb,   g_xz_bf);
    cudaGetSymbolAddress((void**)&p_part2, g_part2);
    cudaGetSymbolAddress((void**)&p_xn,    g_xn_bf);
    cudaGetSymbolAddress((void**)&p_xib,   g_xi_bf);
    cudaGetSymbolAddress((void**)&p_ycat,  g_ycat_bf);
    cudaGetSymbolAddress((void**)&p_wcomb, g_wcomb);
    cudaGetSymbolAddress((void**)&w_in,    g_w_in);
    cudaGetSymbolAddress((void**)&w_xp,    g_w_xp);
    cudaGetSymbolAddress((void**)&w_cat,   g_w_cat);
    cudaGetSymbolAddress((void**)&w_pj,    g_w_pj);

    const int SMEM_128 = 3*(128*72 + 64*128)*2;   // 104448
    const int SMEM_64  = 3*(64*72  + 64*128)*2;   // 76800
    cudaFuncSetAttribute((hgemm<64,128,0>), cudaFuncAttributeMaxDynamicSharedMemorySize, SMEM_128);
    cudaFuncSetAttribute((hgemm<64,64,0>),  cudaFuncAttributeMaxDynamicSharedMemorySize, SMEM_64);
    cudaFuncSetAttribute((hgemm<64,64,1>),  cudaFuncAttributeMaxDynamicSharedMemorySize, SMEM_64);

    // 0+1. merged layernorm + weight conversion
    {
        CvtArgs a;
        const float* srcs[7] = {P[0][0], P[1][0], P[0][3], P[1][3],
                                P[0][8], P[1][8], proj_w};
        bf16raw* dsts[7] = {w_in, w_in+DM*2*DI, w_xp, w_xp+DI*64,
                            w_cat, w_cat+DI*DM, w_pj};
        int sizes[7] = {DM*2*DI, DM*2*DI, DI*64, DI*64, DI*DM, DI*DM, DM*DM};
        int acc = 0;
        for (int i=0;i<7;i++){ a.s[i]=srcs[i]; a.d[i]=dsts[i]; a.off[i]=acc; acc += sizes[i]/4; }
        a.off[7] = acc;
        int cvtBlocks = (acc + 127)/128;
        ln_cvt_kernel<<<NTOK + cvtBlocks, 128>>>(a, acc, x, ln_g, ln_b);
    }

    // 0c. fold: Wcomb = [f_out_w; b_out_w] @ proj_w   (2048 x 512, K=512)
    hgemm<64,64,0><<<dim3(DM/128, 2*DI/64, 1), 128, SMEM_64>>>(
        w_cat, 0, DM,
        w_pj,  0, DM,
        nullptr, 0, DM,
        p_wcomb, 0,
        DM, DM, nullptr, 0, nullptr, 0, 0, 0,0,0);

    // 2. in-proj: xz = xn @ in_w  (4096 x 2048, K=512) -> bf16
    hgemm<64,128,0><<<dim3(2*DI/128, NTOK/128, 2), 128, SMEM_128>>>(
        p_xn, 0, DM,
        w_in, (long)DM*2*DI, 2*DI,
        nullptr, 0, 2*DI,
        p_xzb, (long)NTOK*2*DI,
        2*DI, DM, nullptr, 0, nullptr, 0, 0, 0,0,0);

    // 3. conv + SiLU (vectorized x4)
    conv_kernel<<<dim3(NTOK,1,2), 256>>>(P[0][1], P[0][2], P[1][1], P[1][2]);

    // 4. x_proj split-K x2: z = dir*2 + khalf, 256 CTAs (MT=64)
    hgemm<64,64,1><<<dim3(1, NTOK/64, 4), 128, SMEM_64>>>(
        p_xib, (long)NTOK*DI, DI,
        w_xp,  (long)DI*64,   64,
        p_part2, (long)2*NTOK*64, 64,
        nullptr, 0,
        64, 512, nullptr, 0, nullptr, 0, 0,
        /*sA2=*/512, /*sB2=*/(long)512*64, /*sC2=*/(long)NTOK*64);

    // 5+6. selective scan: fused split-K combine + dt projection -> ycat bf16
    cudaFuncSetAttribute(scan_kernel, cudaFuncAttributeMaxDynamicSharedMemorySize,
                         (int)sizeof(ScanSmem));
    scan_kernel<<<dim3(DI/CH, BB, 2), 256, sizeof(ScanSmem)>>>(
        P[0][6], P[0][7], P[1][6], P[1][7],
        P[0][4], P[0][5], P[1][4], P[1][5]);

    // 7. out = ycat @ Wcomb + proj_b + x  (4096 x 512, K=2048), 256 CTAs
    hgemm<64,64,0><<<dim3(DM/128, NTOK/64, 1), 128, SMEM_64>>>(
        p_ycat, 0, 2*DI,
        p_wcomb, 0, DM,
        (float*)d_out, 0, DM,
        nullptr, 0,
        DM, 2*DI, proj_b, 0, x, DM, 3, 0,0,0);
}

// round 15
// speedup vs baseline: 1.0106x; 1.0106x over previous
#include <cuda_runtime.h>
#include <cuda_bf16.h>
#include <stdint.h>
#include <math.h>

#define BB 2
#define LL 2048
#define DM 512
#define DI 1024
#define DS 16
#define NTOK (BB*LL)   // 4096
#define TCHUNK 32
#define CH 16

typedef unsigned short bf16raw;

static __device__ __forceinline__ bf16raw f2b(float x){
    __nv_bfloat16 h = __float2bfloat16_rn(x);
    return *reinterpret_cast<bf16raw*>(&h);
}
static __device__ __forceinline__ float b2f(bf16raw v){
    __nv_bfloat16 h = *reinterpret_cast<__nv_bfloat16*>(&v);
    return __bfloat162float(h);
}
static __device__ __forceinline__ void cp16(void* dst, const void* src){
    unsigned sa = (unsigned)__cvta_generic_to_shared(dst);
    asm volatile("cp.async.cg.shared.global [%0], [%1], 16;" :: "r"(sa), "l"(src));
}

// ---------------- scratch -------------------------------------------------
__device__ bf16raw g_xz_bf[2][NTOK*2*DI];    // in-proj out (xi|z), bf16
__device__ bf16raw g_xn_bf[NTOK*DM];
__device__ bf16raw g_xi_bf[2][NTOK*DI];      // conv+silu out bf16 (GEMM2 A + scan)
__device__ bf16raw g_ycat_bf[NTOK*2*DI];
__device__ bf16raw g_wcomb[2*DI*DM];         // folded Wcat@Wproj [2048][512]
__device__ float   g_part2[4][NTOK*64];      // GEMM2 split-K partials (summed in scan)
// bf16 weights
__device__ bf16raw g_w_in[2][DM*2*DI];
__device__ bf16raw g_w_xp[2][DI*64];
__device__ bf16raw g_w_cat[2*DI*DM];
__device__ bf16raw g_w_pj[DM*DM];

// ---------------- merged layernorm + weight conversion ---------------------
struct CvtArgs { const float* s[7]; bf16raw* d[7]; int off[8]; };

__global__ __launch_bounds__(128) void ln_cvt_kernel(
    CvtArgs a, int total4,
    const float* __restrict__ x,
    const float* __restrict__ g,
    const float* __restrict__ b)
{
    int tid = threadIdx.x;
    if (blockIdx.x < NTOK){
        int row = blockIdx.x;
        const float4* xr = (const float4*)(x + (long)row*DM);
        float4 v = xr[tid];
        float s = v.x+v.y+v.z+v.w;
        float q = v.x*v.x+v.y*v.y+v.z*v.z+v.w*v.w;
        #pragma unroll
        for (int o=16;o>0;o>>=1){
            s += __shfl_xor_sync(0xffffffffu, s, o);
            q += __shfl_xor_sync(0xffffffffu, q, o);
        }
        __shared__ float ss[4], sq[4];
        int wid = tid>>5, lane = tid&31;
        if (lane==0){ ss[wid]=s; sq[wid]=q; }
        __syncthreads();
        float S = ss[0]+ss[1]+ss[2]+ss[3];
        float Q = sq[0]+sq[1]+sq[2]+sq[3];
        float mu = S*(1.0f/DM);
        float var = Q*(1.0f/DM) - mu*mu;
        float rs = rsqrtf(var + 1e-5f);
        float4 gv = ((const float4*)g)[tid];
        float4 bv = ((const float4*)b)[tid];
        ushort4 o;
        o.x = f2b((v.x-mu)*rs*gv.x + bv.x);
        o.y = f2b((v.y-mu)*rs*gv.y + bv.y);
        o.z = f2b((v.z-mu)*rs*gv.z + bv.z);
        o.w = f2b((v.w-mu)*rs*gv.w + bv.w);
        ((ushort4*)(g_xn_bf + (long)row*DM))[tid] = o;
    } else {
        int i = (blockIdx.x - NTOK)*128 + tid;   // float4 index
        if (i >= total4) return;
        int seg = 0;
        while (i >= a.off[seg+1]) seg++;
        int j = (i - a.off[seg])*4;
        float4 v = *(const float4*)(a.s[seg] + j);
        bf16raw* d = a.d[seg] + j;
        d[0]=f2b(v.x); d[1]=f2b(v.y); d[2]=f2b(v.z); d[3]=f2b(v.w);
    }
}

// ---------------- bf16 tensor-core GEMM -------------------------------------
// 128 threads, 2x2 warp grid, warp tile (MT/2)x64, 3-stage cp.async pipeline.
template<int BK, int MT, int ZS>
__global__ __launch_bounds__(128, 2) void hgemm(
    const bf16raw* __restrict__ Ag, long sA, int lda,
    const bf16raw* __restrict__ Bg, long sB, int ldb,
    float* __restrict__ Cg, long sC, int ldc,
    bf16raw* __restrict__ Obg, long sO,
    int N, int K,
    const float* __restrict__ biasg, long sbias,
    const float* __restrict__ res, int ldres,
    int epi,
    long sA2, long sB2, long sC2)
{
    const int NST = 3;
    int zo, zi;
    if (ZS){ zo = blockIdx.z>>1; zi = blockIdx.z&1; }
    else   { zo = blockIdx.z;    zi = 0; }
    const bf16raw* A = Ag + sA*zo + (ZS ? sA2*zi : 0);
    const bf16raw* B = Bg + sB*zo + (ZS ? sB2*zi : 0);
    float* C   = Cg  ? Cg  + sC*zo + (ZS ? sC2*zi : 0) : nullptr;
    bf16raw* Ob = Obg ? Obg + sO*zo : nullptr;
    const float* bias = biasg ? biasg + sbias*zo : nullptr;

    extern __shared__ __align__(16) bf16raw sdyn[];
    const int ABUF = MT*(BK+8);
    const int BBUF = BK*128;
    bf16raw* As = sdyn;
    bf16raw* Bs = sdyn + NST*ABUF;

    int tid = threadIdx.x;
    int lane = tid & 31, wid = tid >> 5;
    int warp_m = wid & 1, warp_n = wid >> 1;
    int bm = blockIdx.y*MT, bn = blockIdx.x*128;

    const int MTI = MT/32;
    float acc[MTI][8][4];
    #pragma unroll
    for (int a=0;a<MTI;a++) for (int b2=0;b2<8;b2++) for (int c=0;c<4;c++) acc[a][b2][c]=0.f;

    int KT = K / BK;
    const int CPR = BK/8;

    auto loadTile = [&](int kt, int buf){
        int k0 = kt*BK;
        #pragma unroll
        for (int i=0;i<MT*BK/1024;i++){
            int q = tid + i*128;
            int r = q / CPR, c = q % CPR;
            const bf16raw* src = A + (long)(bm+r)*lda + k0 + c*8;
            unsigned sa = (unsigned)__cvta_generic_to_shared(&As[buf*ABUF + r*(BK+8) + c*8]);
            asm volatile("cp.async.cg.shared.global [%0], [%1], 16;\n" :: "r"(sa), "l"(src));
        }
        #pragma unroll
        for (int i=0;i<BK/8;i++){
            int q = tid + i*128;
            int r = q>>4, c = q&15;
            int gcol = bn + c*8;
            const bf16raw* src = B + (long)(k0+r)*ldb + gcol;
            unsigned sa = (unsigned)__cvta_generic_to_shared(&Bs[buf*BBUF + r*128 + ((c ^ (r&7))*8)]);
            int sz = (gcol < N) ? 16 : 0;
            asm volatile("cp.async.cg.shared.global [%0], [%1], 16, %2;\n" :: "r"(sa), "l"(src), "r"(sz));
        }
    };

    #pragma unroll
    for (int p=0; p<NST-1; p++){
        loadTile(p, p);
        asm volatile("cp.async.commit_group;\n" ::: "memory");
    }

    for (int kt=0; kt<KT; kt++){
        asm volatile("cp.async.wait_group %0;\n" :: "n"(NST-2) : "memory");
        __syncthreads();
        int buf = kt % NST;

        #pragma unroll
        for (int ks=0; ks<BK/16; ks++){
            unsigned af[MTI][4];
            #pragma unroll
            for (int mt=0; mt<MTI; mt++){
                int row = warp_m*(MT/2) + mt*16 + (lane&15);
                int chunk = ks*2 + (lane>>4);
                unsigned addr = (unsigned)__cvta_generic_to_shared(&As[buf*ABUF + row*(BK+8) + chunk*8]);
                asm volatile("ldmatrix.sync.aligned.m8n8.x4.shared.b16 {%0,%1,%2,%3}, [%4];"
                    : "=r"(af[mt][0]),"=r"(af[mt][1]),"=r"(af[mt][2]),"=r"(af[mt][3]) : "r"(addr));
            }
            unsigned bfm[8][2];
            #pragma unroll
            for (int jn=0; jn<4; jn++){
                int row = ks*16 + (lane&15);
                int c = warp_n*8 + jn*2 + (lane>>4);
                unsigned addr = (unsigned)__cvta_generic_to_shared(&Bs[buf*BBUF + row*128 + ((c ^ (row&7))*8)]);
                unsigned r0,r1,r2,r3;
                asm volatile("ldmatrix.sync.aligned.m8n8.x4.trans.shared.b16 {%0,%1,%2,%3}, [%4];"
                    : "=r"(r0),"=r"(r1),"=r"(r2),"=r"(r3) : "r"(addr));
                bfm[jn*2][0]=r0;   bfm[jn*2][1]=r1;
                bfm[jn*2+1][0]=r2; bfm[jn*2+1][1]=r3;
            }
            #pragma unroll
            for (int mt=0; mt<MTI; mt++)
                #pragma unroll
                for (int nt=0; nt<8; nt++){
                    asm volatile("mma.sync.aligned.m16n8k16.row.col.f32.bf16.bf16.f32 "
                        "{%0,%1,%2,%3}, {%4,%5,%6,%7}, {%8,%9}, {%0,%1,%2,%3};"
                        : "+f"(acc[mt][nt][0]),"+f"(acc[mt][nt][1]),
                          "+f"(acc[mt][nt][2]),"+f"(acc[mt][nt][3])
                        : "r"(af[mt][0]),"r"(af[mt][1]),"r"(af[mt][2]),"r"(af[mt][3]),
                          "r"(bfm[nt][0]),"r"(bfm[nt][1]));
                }
        }

        int nl = kt + NST - 1;
        if (nl < KT){
            loadTile(nl, nl % NST);
            asm volatile("cp.async.commit_group;\n" ::: "memory");
        } else {
            asm volatile("cp.async.commit_group;\n" ::: "memory");
        }
    }

    #pragma unroll
    for (int mt=0; mt<MTI; mt++){
        #pragma unroll
        for (int i2=0; i2<2; i2++){
            long r = bm + warp_m*(MT/2) + mt*16 + (lane>>2) + i2*8;
            #pragma unroll
            for (int nt=0; nt<8; nt++){
                int cbase = bn + warp_n*64 + nt*8 + (lane&3)*2;
                #pragma unroll
                for (int j=0; j<2; j++){
                    int c = cbase + j;
                    if (c >= N) continue;
                    float v = acc[mt][nt][i2*2+j];
                    if (epi==3){ v += bias[c] + res[r*ldres + c]; }
                    if (C)  C[r*ldc + c] = v;
                    if (Ob) Ob[r*ldc + c] = f2b(v);
                }
            }
        }
    }
}

// ---------------- depthwise conv + SiLU (round-13 form: simple, dense) -----
__global__ void conv_kernel(const float* __restrict__ wf, const float* __restrict__ biasf,
                            const float* __restrict__ wb, const float* __restrict__ biasb){
    int dir = blockIdx.z;
    const float* w    = dir ? wb : wf;
    const float* bias = dir ? biasb : biasf;
    int idx = blockIdx.x*blockDim.x + threadIdx.x;
    int d = idx & (DI-1);
    int t = (idx >> 10) & (LL-1);
    int b = idx >> 21;
    const bf16raw* xz = g_xz_bf[dir];
    float acc = bias[d];
    #pragma unroll
    for (int j=0;j<4;j++){
        int tt = (dir==0) ? (t-3+j) : (t+3-j);
        if (tt>=0 && tt<LL)
            acc = fmaf(w[d*4+j], b2f(xz[((long)(b*LL+tt)*2*DI) + d]), acc);
    }
    float s = acc / (1.f + __expf(-acc));
    g_xi_bf[dir][idx] = f2b(s);
}

// ---------------- selective scan: fused dt proj + split-K combine ----------
struct ScanSmem {
    float   p0[2][TCHUNK][64];   // GEMM2 partial 0
    float   p1[2][TCHUNK][64];   // GEMM2 partial 1
    float   xd[TCHUNK][64];      // summed xdbl: [0:32) dt-in, [32:48) B, [48:64) C
    bf16raw xi[2][TCHUNK][CH];
    bf16raw z [2][TCHUNK][CH];
    float   dtw[32][CH];
    float   dts[TCHUNK][CH];
    float   dtx[TCHUNK][CH];
    float   dtb[CH];
    float   p [TCHUNK][CH][17];
};

__global__ __launch_bounds__(256) void scan_kernel(
    const float* __restrict__ fA, const float* __restrict__ fD,
    const float* __restrict__ bA, const float* __restrict__ bD,
    const float* __restrict__ fdtw, const float* __restrict__ fdtb,
    const float* __restrict__ bdtw, const float* __restrict__ bdtb)
{
    extern __shared__ char smem_raw[];
    ScanSmem* S = reinterpret_cast<ScanSmem*>(smem_raw);

    int dir = blockIdx.z;
    int b   = blockIdx.y;
    int d0  = blockIdx.x * CH;
    const float* A_log = dir ? bA : fA;
    const float* Dp    = dir ? bD : fD;
    const float* dtwg  = dir ? bdtw : fdtw;
    const float* dtbg  = dir ? bdtb : fdtb;

    int tid  = threadIdx.x;
    int wid  = tid >> 5, lane = tid & 31;
    int half = lane >> 4, n = lane & 15;
    int dl   = wid*2 + half;

    float a    = -expf(A_log[(d0+dl)*DS + n]);
    float Dv_r = Dp[d0 + (tid & 15)];

    #pragma unroll
    for (int i=0;i<2;i++){
        int q = tid + i*256;
        S->dtw[q>>4][q&15] = dtwg[(long)(q>>4)*DI + d0 + (q&15)];
    }
    if (tid < CH) S->dtb[tid] = dtbg[d0 + tid];

    const bf16raw* xip = g_xi_bf[dir];
    const bf16raw* xzp = g_xz_bf[dir];
    const float*   pp0 = g_part2[dir*2+0];
    const float*   pp1 = g_part2[dir*2+1];

    const int NCH = LL / TCHUNK;

    auto loadChunk = [&](int c, int buf){
        #pragma unroll
        for (int i=0;i<2;i++){
            int q = tid + i*256;
            int row = q >> 4, seg = q & 15;
            int trow = (dir==0) ? c*TCHUNK+row : (LL-1) - (c*TCHUNK+row);
            long tok = (long)b*LL + trow;
            cp16(&S->p0[buf][row][seg*4], pp0 + tok*64 + seg*4);
            cp16(&S->p1[buf][row][seg*4], pp1 + tok*64 + seg*4);
        }
        if (tid < 64){
            int row = tid >> 1, seg = tid & 1;
            int trow = (dir==0) ? c*TCHUNK+row : (LL-1) - (c*TCHUNK+row);
            long tok = (long)b*LL + trow;
            cp16(&S->xi[buf][row][seg*8], xip + tok*DI + d0 + seg*8);
        } else if (tid < 128){
            int rem = tid - 64;
            int row = rem >> 1, seg = rem & 1;
            int trow = (dir==0) ? c*TCHUNK+row : (LL-1) - (c*TCHUNK+row);
            long tok = (long)b*LL + trow;
            cp16(&S->z[buf][row][seg*8], xzp + tok*2*DI + DI + d0 + seg*8);
        }
    };

    float h = 0.f;
    loadChunk(0, 0);
    asm volatile("cp.async.commit_group;\n" ::: "memory");

    for (int c=0; c<NCH; c++){
        if (c+1 < NCH) loadChunk(c+1, (c+1)&1);
        asm volatile("cp.async.commit_group;\n" ::: "memory");
        asm volatile("cp.async.wait_group 1;\n" ::: "memory");
        __syncthreads();
        int buf = c & 1;

        // ---- phase A0: split-K combine -> xd ----
        #pragma unroll
        for (int r=0;r<8;r++){
            int q = tid + r*256;
            int s = q >> 6, col = q & 63;
            S->xd[s][col] = S->p0[buf][s][col] + S->p1[buf][s][col];
        }
        __syncthreads();

        // ---- phase A: dt projection + dtx = dt*xi ----
        #pragma unroll
        for (int rep=0; rep<2; rep++){
            int o = tid + rep*256;
            int s = o >> 4, dlo = o & 15;
            float acc = S->dtb[dlo];
            #pragma unroll
            for (int k=0;k<32;k++) acc = fmaf(S->xd[s][k], S->dtw[k][dlo], acc);
            float dtv = (acc > 20.f) ? acc : log1pf(__expf(acc));
            S->dts[s][dlo] = dtv;
            S->dtx[s][dlo] = dtv * b2f(S->xi[buf][s][dlo]);
        }
        __syncthreads();

        // ---- serial recurrence ----
        #pragma unroll
        for (int s=0; s<TCHUNK; s++){
            float dtv = S->dts[s][dl];
            float dtx = S->dtx[s][dl];
            float Bt  = S->xd[s][32+n];
            float Ct  = S->xd[s][48+n];
            float dA  = __expf(dtv * a);
            h = fmaf(dA, h, dtx*Bt);
            S->p[s][dl][n] = h * Ct;
        }
        __syncthreads();

        // ---- reduction + epilogue + store ----
        #pragma unroll
        for (int rep=0; rep<2; rep++){
            int o  = tid + rep*256;
            int s  = o >> 4, dlo = o & 15;
            float sum = 0.f;
            #pragma unroll
            for (int k=0;k<16;k++) sum += S->p[s][dlo][k];
            float xiv = b2f(S->xi[buf][s][dlo]);
            float zv  = b2f(S->z[buf][s][dlo]);
            float yv  = (sum + xiv*Dv_r) * zv / (1.f + __expf(-zv));
            int trow  = (dir==0) ? c*TCHUNK+s : (LL-1) - (c*TCHUNK+s);
            g_ycat_bf[((long)b*LL + trow)*2*DI + dir*DI + d0 + dlo] = f2b(yv);
        }
        __syncthreads();
    }
}

// ---------------- host launcher --------------------------------------------
extern "C" void kernel_launch(void* const* d_in, const int* in_sizes, int n_in,
                              void* d_out, int out_size){
    const float* x      = (const float*)d_in[0];
    const float* ln_g   = (const float*)d_in[1];
    const float* ln_b   = (const float*)d_in[2];
    const float* proj_w = (const float*)d_in[3];
    const float* proj_b = (const float*)d_in[4];
    const float* P[2][9];
    for (int dir=0; dir<2; dir++)
        for (int i=0;i<9;i++)
            P[dir][i] = (const float*)d_in[5 + dir*9 + i];

    float   *p_part2;
    bf16raw *p_xzb,*p_xn,*p_xib,*p_ycat,*p_wcomb;
    bf16raw *w_in,*w_xp,*w_cat,*w_pj;
    cudaGetSymbolAddress((void**)&p_xzb,   g_xz_bf);
    cudaGetSymbolAddress((void**)&p_part2, g_part2);
    cudaGetSymbolAddress((void**)&p_xn,    g_xn_bf);
    cudaGetSymbolAddress((void**)&p_xib,   g_xi_bf);
    cudaGetSymbolAddress((void**)&p_ycat,  g_ycat_bf);
    cudaGetSymbolAddress((void**)&p_wcomb, g_wcomb);
    cudaGetSymbolAddress((void**)&w_in,    g_w_in);
    cudaGetSymbolAddress((void**)&w_xp,    g_w_xp);
    cudaGetSymbolAddress((void**)&w_cat,   g_w_cat);
    cudaGetSymbolAddress((void**)&w_pj,    g_w_pj);

    const int SMEM_128 = 3*(128*72 + 64*128)*2;   // 104448
    const int SMEM_64  = 3*(64*72  + 64*128)*2;   // 76800
    cudaFuncSetAttribute((hgemm<64,128,0>), cudaFuncAttributeMaxDynamicSharedMemorySize, SMEM_128);
    cudaFuncSetAttribute((hgemm<64,64,0>),  cudaFuncAttributeMaxDynamicSharedMemorySize, SMEM_64);
    cudaFuncSetAttribute((hgemm<64,64,1>),  cudaFuncAttributeMaxDynamicSharedMemorySize, SMEM_64);

    // 0+1. merged layernorm + weight conversion
    {
        CvtArgs a;
        const float* srcs[7] = {P[0][0], P[1][0], P[0][3], P[1][3],
                                P[0][8], P[1][8], proj_w};
        bf16raw* dsts[7] = {w_in, w_in+DM*2*DI, w_xp, w_xp+DI*64,
                            w_cat, w_cat+DI*DM, w_pj};
        int sizes[7] = {DM*2*DI, DM*2*DI, DI*64, DI*64, DI*DM, DI*DM, DM*DM};
        int acc = 0;
        for (int i=0;i<7;i++){ a.s[i]=srcs[i]; a.d[i]=dsts[i]; a.off[i]=acc; acc += sizes[i]/4; }
        a.off[7] = acc;
        int cvtBlocks = (acc + 127)/128;
        ln_cvt_kernel<<<NTOK + cvtBlocks, 128>>>(a, acc, x, ln_g, ln_b);
    }

    // 0c. fold: Wcomb = [f_out_w; b_out_w] @ proj_w   (2048 x 512, K=512)
    hgemm<64,64,0><<<dim3(DM/128, 2*DI/64, 1), 128, SMEM_64>>>(
        w_cat, 0, DM,
        w_pj,  0, DM,
        nullptr, 0, DM,
        p_wcomb, 0,
        DM, DM, nullptr, 0, nullptr, 0, 0, 0,0,0);

    // 2. in-proj: xz = xn @ in_w  (4096 x 2048, K=512) -> bf16
    hgemm<64,128,0><<<dim3(2*DI/128, NTOK/128, 2), 128, SMEM_128>>>(
        p_xn, 0, DM,
        w_in, (long)DM*2*DI, 2*DI,
        nullptr, 0, 2*DI,
        p_xzb, (long)NTOK*2*DI,
        2*DI, DM, nullptr, 0, nullptr, 0, 0, 0,0,0);

    // 3. conv + SiLU (round-13 dense form)
    conv_kernel<<<dim3(NTOK*DI/256,1,2), 256>>>(P[0][1], P[0][2], P[1][1], P[1][2]);

    // 4. x_proj split-K x2: z = dir*2 + khalf, 256 CTAs (MT=64)
    hgemm<64,64,1><<<dim3(1, NTOK/64, 4), 128, SMEM_64>>>(
        p_xib, (long)NTOK*DI, DI,
        w_xp,  (long)DI*64,   64,
        p_part2, (long)2*NTOK*64, 64,
        nullptr, 0,
        64, 512, nullptr, 0, nullptr, 0, 0,
        /*sA2=*/512, /*sB2=*/(long)512*64, /*sC2=*/(long)NTOK*64);

    // 5+6. selective scan: fused split-K combine + dt projection -> ycat bf16
    cudaFuncSetAttribute(scan_kernel, cudaFuncAttributeMaxDynamicSharedMemorySize,
                         (int)sizeof(ScanSmem));
    scan_kernel<<<dim3(DI/CH, BB, 2), 256, sizeof(ScanSmem)>>>(
        P[0][6], P[0][7], P[1][6], P[1][7],
        P[0][4], P[0][5], P[1][4], P[1][5]);

    // 7. out = ycat @ Wcomb + proj_b + x  (4096 x 512, K=2048), 256 CTAs
    hgemm<64,64,0><<<dim3(DM/128, NTOK/64, 1), 128, SMEM_64>>>(
        p_ycat, 0, 2*DI,
        p_wcomb, 0, DM,
        (float*)d_out, 0, DM,
        nullptr, 0,
        DM, 2*DI, proj_b, 0, x, DM, 3, 0,0,0);
}

// round 16
// speedup vs baseline: 1.1020x; 1.0904x over previous
#include <cuda_runtime.h>
#include <cuda_bf16.h>
#include <stdint.h>
#include <math.h>

#define BB 2
#define LL 2048
#define DM 512
#define DI 1024
#define DS 16
#define NTOK (BB*LL)   // 4096
#define TCHUNK 32
#define CH 16

typedef unsigned short bf16raw;

static __device__ __forceinline__ bf16raw f2b(float x){
    __nv_bfloat16 h = __float2bfloat16_rn(x);
    return *reinterpret_cast<bf16raw*>(&h);
}
static __device__ __forceinline__ float b2f(bf16raw v){
    __nv_bfloat16 h = *reinterpret_cast<__nv_bfloat16*>(&v);
    return __bfloat162float(h);
}
static __device__ __forceinline__ void cp16(void* dst, const void* src){
    unsigned sa = (unsigned)__cvta_generic_to_shared(dst);
    asm volatile("cp.async.cg.shared.global [%0], [%1], 16;" :: "r"(sa), "l"(src));
}

// ---------------- scratch -------------------------------------------------
__device__ bf16raw g_xz_bf[2][NTOK*2*DI];    // in-proj out (xi|z), bf16
__device__ float   g_xdbl[2][NTOK*64];       // x_proj out fp32 (scan: dt-in|B|C)
__device__ bf16raw g_xn_bf[NTOK*DM];
__device__ bf16raw g_xi_bf[2][NTOK*DI];      // conv+silu out bf16 (GEMM2 A + scan)
__device__ bf16raw g_ycat_bf[NTOK*2*DI];
__device__ bf16raw g_wcomb[2*DI*DM];         // folded Wcat@Wproj [2048][512]
__device__ float   g_part2[4][NTOK*64];      // GEMM2 split-K partials
// bf16 weights
__device__ bf16raw g_w_in[2][DM*2*DI];
__device__ bf16raw g_w_xp[2][DI*64];
__device__ bf16raw g_w_cat[2*DI*DM];
__device__ bf16raw g_w_pj[DM*DM];

// ---------------- fused fp32 -> bf16 conversion ----------------------------
struct CvtArgs { const float* s[9]; bf16raw* d[9]; int off[10]; };

__global__ void cvt_all_kernel(CvtArgs a, int total4){
    int i = blockIdx.x*blockDim.x + threadIdx.x;
    if (i >= total4) return;
    int seg = 0;
    while (i >= a.off[seg+1]) seg++;
    int j = (i - a.off[seg])*4;
    float4 v = *(const float4*)(a.s[seg] + j);
    bf16raw* d = a.d[seg] + j;
    d[0]=f2b(v.x); d[1]=f2b(v.y); d[2]=f2b(v.z); d[3]=f2b(v.w);
}

// ---------------- layernorm: float4 + warp shuffle -------------------------
__global__ __launch_bounds__(128) void ln_kernel(const float* __restrict__ x,
                          const float* __restrict__ g,
                          const float* __restrict__ b) {
    int row = blockIdx.x;
    int tid = threadIdx.x;
    const float4* xr = (const float4*)(x + (long)row*DM);
    float4 v = xr[tid];
    float s = v.x+v.y+v.z+v.w;
    float q = v.x*v.x+v.y*v.y+v.z*v.z+v.w*v.w;
    #pragma unroll
    for (int o=16;o>0;o>>=1){
        s += __shfl_xor_sync(0xffffffffu, s, o);
        q += __shfl_xor_sync(0xffffffffu, q, o);
    }
    __shared__ float ss[4], sq[4];
    int wid = tid>>5, lane = tid&31;
    if (lane==0){ ss[wid]=s; sq[wid]=q; }
    __syncthreads();
    float S = ss[0]+ss[1]+ss[2]+ss[3];
    float Q = sq[0]+sq[1]+sq[2]+sq[3];
    float mu = S*(1.0f/DM);
    float var = Q*(1.0f/DM) - mu*mu;
    float rs = rsqrtf(var + 1e-5f);
    float4 gv = ((const float4*)g)[tid];
    float4 bv = ((const float4*)b)[tid];
    ushort4 o;
    o.x = f2b((v.x-mu)*rs*gv.x + bv.x);
    o.y = f2b((v.y-mu)*rs*gv.y + bv.y);
    o.z = f2b((v.z-mu)*rs*gv.z + bv.z);
    o.w = f2b((v.w-mu)*rs*gv.w + bv.w);
    ((ushort4*)(g_xn_bf + (long)row*DM))[tid] = o;
}

// ---------------- bf16 tensor-core GEMM -------------------------------------
// 128 threads, 2x2 warp grid, warp tile (MT/2)x64, 3-stage cp.async pipeline.
template<int BK, int MT, int ZS>
__global__ __launch_bounds__(128, 2) void hgemm(
    const bf16raw* __restrict__ Ag, long sA, int lda,
    const bf16raw* __restrict__ Bg, long sB, int ldb,
    float* __restrict__ Cg, long sC, int ldc,
    bf16raw* __restrict__ Obg, long sO,
    int N, int K,
    const float* __restrict__ biasg, long sbias,
    const float* __restrict__ res, int ldres,
    int epi,
    long sA2, long sB2, long sC2)
{
    const int NST = 3;
    int zo, zi;
    if (ZS){ zo = blockIdx.z>>1; zi = blockIdx.z&1; }
    else   { zo = blockIdx.z;    zi = 0; }
    const bf16raw* A = Ag + sA*zo + (ZS ? sA2*zi : 0);
    const bf16raw* B = Bg + sB*zo + (ZS ? sB2*zi : 0);
    float* C   = Cg  ? Cg  + sC*zo + (ZS ? sC2*zi : 0) : nullptr;
    bf16raw* Ob = Obg ? Obg + sO*zo : nullptr;
    const float* bias = biasg ? biasg + sbias*zo : nullptr;

    extern __shared__ __align__(16) bf16raw sdyn[];
    const int ABUF = MT*(BK+8);
    const int BBUF = BK*128;
    bf16raw* As = sdyn;
    bf16raw* Bs = sdyn + NST*ABUF;

    int tid = threadIdx.x;
    int lane = tid & 31, wid = tid >> 5;
    int warp_m = wid & 1, warp_n = wid >> 1;
    int bm = blockIdx.y*MT, bn = blockIdx.x*128;

    const int MTI = MT/32;
    float acc[MTI][8][4];
    #pragma unroll
    for (int a=0;a<MTI;a++) for (int b2=0;b2<8;b2++) for (int c=0;c<4;c++) acc[a][b2][c]=0.f;

    int KT = K / BK;
    const int CPR = BK/8;

    auto loadTile = [&](int kt, int buf){
        int k0 = kt*BK;
        #pragma unroll
        for (int i=0;i<MT*BK/1024;i++){
            int q = tid + i*128;
            int r = q / CPR, c = q % CPR;
            const bf16raw* src = A + (long)(bm+r)*lda + k0 + c*8;
            unsigned sa = (unsigned)__cvta_generic_to_shared(&As[buf*ABUF + r*(BK+8) + c*8]);
            asm volatile("cp.async.cg.shared.global [%0], [%1], 16;\n" :: "r"(sa), "l"(src));
        }
        #pragma unroll
        for (int i=0;i<BK/8;i++){
            int q = tid + i*128;
            int r = q>>4, c = q&15;
            int gcol = bn + c*8;
            const bf16raw* src = B + (long)(k0+r)*ldb + gcol;
            unsigned sa = (unsigned)__cvta_generic_to_shared(&Bs[buf*BBUF + r*128 + ((c ^ (r&7))*8)]);
            int sz = (gcol < N) ? 16 : 0;
            asm volatile("cp.async.cg.shared.global [%0], [%1], 16, %2;\n" :: "r"(sa), "l"(src), "r"(sz));
        }
    };

    #pragma unroll
    for (int p=0; p<NST-1; p++){
        loadTile(p, p);
        asm volatile("cp.async.commit_group;\n" ::: "memory");
    }

    for (int kt=0; kt<KT; kt++){
        asm volatile("cp.async.wait_group %0;\n" :: "n"(NST-2) : "memory");
        __syncthreads();
        int buf = kt % NST;

        #pragma unroll
        for (int ks=0; ks<BK/16; ks++){
            unsigned af[MTI][4];
            #pragma unroll
            for (int mt=0; mt<MTI; mt++){
                int row = warp_m*(MT/2) + mt*16 + (lane&15);
                int chunk = ks*2 + (lane>>4);
                unsigned addr = (unsigned)__cvta_generic_to_shared(&As[buf*ABUF + row*(BK+8) + chunk*8]);
                asm volatile("ldmatrix.sync.aligned.m8n8.x4.shared.b16 {%0,%1,%2,%3}, [%4];"
                    : "=r"(af[mt][0]),"=r"(af[mt][1]),"=r"(af[mt][2]),"=r"(af[mt][3]) : "r"(addr));
            }
            unsigned bfm[8][2];
            #pragma unroll
            for (int jn=0; jn<4; jn++){
                int row = ks*16 + (lane&15);
                int c = warp_n*8 + jn*2 + (lane>>4);
                unsigned addr = (unsigned)__cvta_generic_to_shared(&Bs[buf*BBUF + row*128 + ((c ^ (row&7))*8)]);
                unsigned r0,r1,r2,r3;
                asm volatile("ldmatrix.sync.aligned.m8n8.x4.trans.shared.b16 {%0,%1,%2,%3}, [%4];"
                    : "=r"(r0),"=r"(r1),"=r"(r2),"=r"(r3) : "r"(addr));
                bfm[jn*2][0]=r0;   bfm[jn*2][1]=r1;
                bfm[jn*2+1][0]=r2; bfm[jn*2+1][1]=r3;
            }
            #pragma unroll
            for (int mt=0; mt<MTI; mt++)
                #pragma unroll
                for (int nt=0; nt<8; nt++){
                    asm volatile("mma.sync.aligned.m16n8k16.row.col.f32.bf16.bf16.f32 "
                        "{%0,%1,%2,%3}, {%4,%5,%6,%7}, {%8,%9}, {%0,%1,%2,%3};"
                        : "+f"(acc[mt][nt][0]),"+f"(acc[mt][nt][1]),
                          "+f"(acc[mt][nt][2]),"+f"(acc[mt][nt][3])
                        : "r"(af[mt][0]),"r"(af[mt][1]),"r"(af[mt][2]),"r"(af[mt][3]),
                          "r"(bfm[nt][0]),"r"(bfm[nt][1]));
                }
        }

        int nl = kt + NST - 1;
        if (nl < KT){
            loadTile(nl, nl % NST);
            asm volatile("cp.async.commit_group;\n" ::: "memory");
        } else {
            asm volatile("cp.async.commit_group;\n" ::: "memory");
        }
    }

    #pragma unroll
    for (int mt=0; mt<MTI; mt++){
        #pragma unroll
        for (int i2=0; i2<2; i2++){
            long r = bm + warp_m*(MT/2) + mt*16 + (lane>>2) + i2*8;
            #pragma unroll
            for (int nt=0; nt<8; nt++){
                int cbase = bn + warp_n*64 + nt*8 + (lane&3)*2;
                #pragma unroll
                for (int j=0; j<2; j++){
                    int c = cbase + j;
                    if (c >= N) continue;
                    float v = acc[mt][nt][i2*2+j];
                    if (epi==3){ v += bias[c] + res[r*ldres + c]; }
                    if (C)  C[r*ldc + c] = v;
                    if (Ob) Ob[r*ldc + c] = f2b(v);
                }
            }
        }
    }
}

// ---------------- GEMM2 split-K combine: xdbl = p0+p1 (fp32) ---------------
__global__ void combine2_kernel(){
    int i = (blockIdx.x*blockDim.x + threadIdx.x)*4;   // over 2*NTOK*64
    int dir = (i >= NTOK*64) ? 1 : 0;
    int j = i - dir*(NTOK*64);
    float4 a = *(const float4*)(&g_part2[dir*2+0][j]);
    float4 b = *(const float4*)(&g_part2[dir*2+1][j]);
    float4 o;
    o.x=a.x+b.x; o.y=a.y+b.y; o.z=a.z+b.z; o.w=a.w+b.w;
    *(float4*)(&g_xdbl[dir][j]) = o;
}

// ---------------- depthwise conv + SiLU: sliding window, 4 t-outputs/thread -
__global__ __launch_bounds__(256) void conv_kernel(
    const float* __restrict__ wf, const float* __restrict__ biasf,
    const float* __restrict__ wb, const float* __restrict__ biasb)
{
    int dir = blockIdx.z;
    const float* w    = dir ? wb : wf;
    const float* bias = dir ? biasb : biasf;
    int q = blockIdx.x*blockDim.x + threadIdx.x;   // over NTOK*DI/4
    int d    = q & (DI-1);
    int tblk = (q >> 10) & (LL/4 - 1);
    int b    = q >> 19;
    int t0   = tblk*4;
    const bf16raw* xz = g_xz_bf[dir];

    float w0=w[d*4+0], w1=w[d*4+1], w2=w[d*4+2], w3=w[d*4+3];
    float bv = bias[d];

    // window: v[i] = x[t0 - 3 + i] (fwd)  or  x[t0 + i] (bwd), i in 0..6
    float v[7];
    #pragma unroll
    for (int i=0;i<7;i++){
        int tt = (dir==0) ? (t0 - 3 + i) : (t0 + i);
        v[i] = (tt >= 0 && tt < LL)
             ? b2f(xz[((long)(b*LL + tt)*2*DI) + d]) : 0.f;
    }

    bf16raw out[4];
    #pragma unroll
    for (int s=0;s<4;s++){
        float acc;
        if (dir==0)   // y[t0+s] = Σ_j w[j] * v[s+j]
            acc = fmaf(w0, v[s], fmaf(w1, v[s+1], fmaf(w2, v[s+2], fmaf(w3, v[s+3], bv))));
        else          // y[t0+s] = Σ_j w[j] * v[s+3-j]
            acc = fmaf(w0, v[s+3], fmaf(w1, v[s+2], fmaf(w2, v[s+1], fmaf(w3, v[s], bv))));
        out[s] = f2b(acc / (1.f + __expf(-acc)));
    }
    #pragma unroll
    for (int s=0;s<4;s++)
        g_xi_bf[dir][((long)(b*LL + t0 + s))*DI + d] = out[s];
}

// ---------------- selective scan + fused dt projection (round-13 form) -----
struct ScanSmem {
    float   xd[2][TCHUNK][64];   // xdbl row: [0:32) dt-in, [32:48) B, [48:64) C
    bf16raw xi[2][TCHUNK][CH];
    bf16raw z [2][TCHUNK][CH];
    float   dtw[32][CH];
    float   dts[TCHUNK][CH];
    float   dtx[TCHUNK][CH];
    float   dtb[CH];
    float   p [TCHUNK][CH][17];
};

__global__ __launch_bounds__(256) void scan_kernel(
    const float* __restrict__ fA, const float* __restrict__ fD,
    const float* __restrict__ bA, const float* __restrict__ bD,
    const float* __restrict__ fdtw, const float* __restrict__ fdtb,
    const float* __restrict__ bdtw, const float* __restrict__ bdtb)
{
    extern __shared__ char smem_raw[];
    ScanSmem* S = reinterpret_cast<ScanSmem*>(smem_raw);

    int dir = blockIdx.z;
    int b   = blockIdx.y;
    int d0  = blockIdx.x * CH;
    const float* A_log = dir ? bA : fA;
    const float* Dp    = dir ? bD : fD;
    const float* dtwg  = dir ? bdtw : fdtw;
    const float* dtbg  = dir ? bdtb : fdtb;

    int tid  = threadIdx.x;
    int wid  = tid >> 5, lane = tid & 31;
    int half = lane >> 4, n = lane & 15;
    int dl   = wid*2 + half;

    float a    = -expf(A_log[(d0+dl)*DS + n]);
    float Dv_r = Dp[d0 + (tid & 15)];

    #pragma unroll
    for (int i=0;i<2;i++){
        int q = tid + i*256;
        S->dtw[q>>4][q&15] = dtwg[(long)(q>>4)*DI + d0 + (q&15)];
    }
    if (tid < CH) S->dtb[tid] = dtbg[d0 + tid];

    const bf16raw* xip = g_xi_bf[dir];
    const bf16raw* xzp = g_xz_bf[dir];
    const float*   bcp = g_xdbl[dir];

    const int NCH = LL / TCHUNK;

    auto loadChunk = [&](int c, int buf){
        {
            #pragma unroll
            for (int i=0;i<2;i++){
                int q = tid + i*256;
                int row = q >> 4, seg = q & 15;
                int trow = (dir==0) ? c*TCHUNK+row : (LL-1) - (c*TCHUNK+row);
                long tok = (long)b*LL + trow;
                cp16(&S->xd[buf][row][seg*4], bcp + tok*64 + seg*4);
            }
        }
        if (tid < 64){
            int row = tid >> 1, seg = tid & 1;
            int trow = (dir==0) ? c*TCHUNK+row : (LL-1) - (c*TCHUNK+row);
            long tok = (long)b*LL + trow;
            cp16(&S->xi[buf][row][seg*8], xip + tok*DI + d0 + seg*8);
        } else if (tid < 128){
            int rem = tid - 64;
            int row = rem >> 1, seg = rem & 1;
            int trow = (dir==0) ? c*TCHUNK+row : (LL-1) - (c*TCHUNK+row);
            long tok = (long)b*LL + trow;
            cp16(&S->z[buf][row][seg*8], xzp + tok*2*DI + DI + d0 + seg*8);
        }
    };

    float h = 0.f;
    loadChunk(0, 0);
    asm volatile("cp.async.commit_group;\n" ::: "memory");

    for (int c=0; c<NCH; c++){
        if (c+1 < NCH) loadChunk(c+1, (c+1)&1);
        asm volatile("cp.async.commit_group;\n" ::: "memory");
        asm volatile("cp.async.wait_group 1;\n" ::: "memory");
        __syncthreads();
        int buf = c & 1;

        // ---- pre-phase: dt projection + dtx = dt*xi ----
        #pragma unroll
        for (int rep=0; rep<2; rep++){
            int o = tid + rep*256;
            int s = o >> 4, dlo = o & 15;
            float acc = S->dtb[dlo];
            #pragma unroll
            for (int k=0;k<32;k++) acc = fmaf(S->xd[buf][s][k], S->dtw[k][dlo], acc);
            float dtv = (acc > 20.f) ? acc : log1pf(__expf(acc));
            S->dts[s][dlo] = dtv;
            S->dtx[s][dlo] = dtv * b2f(S->xi[buf][s][dlo]);
        }
        __syncthreads();

        // ---- serial recurrence ----
        #pragma unroll
        for (int s=0; s<TCHUNK; s++){
            float dtv = S->dts[s][dl];
            float dtx = S->dtx[s][dl];
            float Bt  = S->xd[buf][s][32+n];
            float Ct  = S->xd[buf][s][48+n];
            float dA  = __expf(dtv * a);
            h = fmaf(dA, h, dtx*Bt);
            S->p[s][dl][n] = h * Ct;
        }
        __syncthreads();

        // ---- reduction + epilogue + store ----
        #pragma unroll
        for (int rep=0; rep<2; rep++){
            int o  = tid + rep*256;
            int s  = o >> 4, dlo = o & 15;
            float sum = 0.f;
            #pragma unroll
            for (int k=0;k<16;k++) sum += S->p[s][dlo][k];
            float xiv = b2f(S->xi[buf][s][dlo]);
            float zv  = b2f(S->z[buf][s][dlo]);
            float yv  = (sum + xiv*Dv_r) * zv / (1.f + __expf(-zv));
            int trow  = (dir==0) ? c*TCHUNK+s : (LL-1) - (c*TCHUNK+s);
            g_ycat_bf[((long)b*LL + trow)*2*DI + dir*DI + d0 + dlo] = f2b(yv);
        }
        __syncthreads();
    }
}

// ---------------- host launcher --------------------------------------------
extern "C" void kernel_launch(void* const* d_in, const int* in_sizes, int n_in,
                              void* d_out, int out_size){
    const float* x      = (const float*)d_in[0];
    const float* ln_g   = (const float*)d_in[1];
    const float* ln_b   = (const float*)d_in[2];
    const float* proj_w = (const float*)d_in[3];
    const float* proj_b = (const float*)d_in[4];
    const float* P[2][9];
    for (int dir=0; dir<2; dir++)
        for (int i=0;i<9;i++)
            P[dir][i] = (const float*)d_in[5 + dir*9 + i];

    float   *p_xdbl,*p_part2;
    bf16raw *p_xzb,*p_xn,*p_xib,*p_ycat,*p_wcomb;
    bf16raw *w_in,*w_xp,*w_cat,*w_pj;
    cudaGetSymbolAddress((void**)&p_xzb,   g_xz_bf);
    cudaGetSymbolAddress((void**)&p_xdbl,  g_xdbl);
    cudaGetSymbolAddress((void**)&p_part2, g_part2);
    cudaGetSymbolAddress((void**)&p_xn,    g_xn_bf);
    cudaGetSymbolAddress((void**)&p_xib,   g_xi_bf);
    cudaGetSymbolAddress((void**)&p_ycat,  g_ycat_bf);
    cudaGetSymbolAddress((void**)&p_wcomb, g_wcomb);
    cudaGetSymbolAddress((void**)&w_in,    g_w_in);
    cudaGetSymbolAddress((void**)&w_xp,    g_w_xp);
    cudaGetSymbolAddress((void**)&w_cat,   g_w_cat);
    cudaGetSymbolAddress((void**)&w_pj,    g_w_pj);

    const int SMEM_128 = 3*(128*72 + 64*128)*2;   // 104448
    const int SMEM_64  = 3*(64*72  + 64*128)*2;   // 76800
    cudaFuncSetAttribute((hgemm<64,128,0>), cudaFuncAttributeMaxDynamicSharedMemorySize, SMEM_128);
    cudaFuncSetAttribute((hgemm<64,64,0>),  cudaFuncAttributeMaxDynamicSharedMemorySize, SMEM_64);
    cudaFuncSetAttribute((hgemm<64,64,1>),  cudaFuncAttributeMaxDynamicSharedMemorySize, SMEM_64);

    // 0. fused weight conversion (dt_w stays fp32 for the fused scan)
    {
        CvtArgs a;
        const float* srcs[7] = {P[0][0], P[1][0], P[0][3], P[1][3],
                                P[0][8], P[1][8], proj_w};
        bf16raw* dsts[7] = {w_in, w_in+DM*2*DI, w_xp, w_xp+DI*64,
                            w_cat, w_cat+DI*DM, w_pj};
        int sizes[7] = {DM*2*DI, DM*2*DI, DI*64, DI*64, DI*DM, DI*DM, DM*DM};
        int acc = 0;
        for (int i=0;i<7;i++){ a.s[i]=srcs[i]; a.d[i]=dsts[i]; a.off[i]=acc; acc += sizes[i]/4; }
        for (int i=7;i<10;i++) a.off[i] = acc;
        cvt_all_kernel<<<(acc+255)/256, 256>>>(a, acc);
    }

    // 0c. fold: Wcomb = [f_out_w; b_out_w] @ proj_w   (2048 x 512, K=512)
    hgemm<64,64,0><<<dim3(DM/128, 2*DI/64, 1), 128, SMEM_64>>>(
        w_cat, 0, DM,
        w_pj,  0, DM,
        nullptr, 0, DM,
        p_wcomb, 0,
        DM, DM, nullptr, 0, nullptr, 0, 0, 0,0,0);

    // 1. layernorm -> bf16
    ln_kernel<<<NTOK, 128>>>(x, ln_g, ln_b);

    // 2. in-proj: xz = xn @ in_w  (4096 x 2048, K=512) -> bf16
    hgemm<64,128,0><<<dim3(2*DI/128, NTOK/128, 2), 128, SMEM_128>>>(
        p_xn, 0, DM,
        w_in, (long)DM*2*DI, 2*DI,
        nullptr, 0, 2*DI,
        p_xzb, (long)NTOK*2*DI,
        2*DI, DM, nullptr, 0, nullptr, 0, 0, 0,0,0);

    // 3. conv + SiLU (sliding-window, 4 outputs/thread)
    conv_kernel<<<dim3(NTOK*DI/4/256,1,2), 256>>>(P[0][1], P[0][2], P[1][1], P[1][2]);

    // 4. x_proj split-K x2: z = dir*2 + khalf, 256 CTAs (MT=64)
    hgemm<64,64,1><<<dim3(1, NTOK/64, 4), 128, SMEM_64>>>(
        p_xib, (long)NTOK*DI, DI,
        w_xp,  (long)DI*64,   64,
        p_part2, (long)2*NTOK*64, 64,
        nullptr, 0,
        64, 512, nullptr, 0, nullptr, 0, 0,
        /*sA2=*/512, /*sB2=*/(long)512*64, /*sC2=*/(long)NTOK*64);

    // 4b. combine partials -> xdbl fp32
    combine2_kernel<<<2*NTOK*64/1024, 256>>>();

    // 5+6. selective scan with fused dt projection -> ycat bf16
    cudaFuncSetAttribute(scan_kernel, cudaFuncAttributeMaxDynamicSharedMemorySize,
                         (int)sizeof(ScanSmem));
    scan_kernel<<<dim3(DI/CH, BB, 2), 256, sizeof(ScanSmem)>>>(
        P[0][6], P[0][7], P[1][6], P[1][7],
        P[0][4], P[0][5], P[1][4], P[1][5]);

    // 7. out = ycat @ Wcomb + proj_b + x  (4096 x 512, K=2048), 256 CTAs
    hgemm<64,64,0><<<dim3(DM/128, NTOK/64, 1), 128, SMEM_64>>>(
        p_ycat, 0, 2*DI,
        p_wcomb, 0, DM,
        (float*)d_out, 0, DM,
        nullptr, 0,
        DM, 2*DI, proj_b, 0, x, DM, 3, 0,0,0);
}

// round 17
// speedup vs baseline: 1.1188x; 1.0152x over previous
#include <cuda_runtime.h>
#include <cuda_bf16.h>
#include <stdint.h>
#include <math.h>

#define BB 2
#define LL 2048
#define DM 512
#define DI 1024
#define DS 16
#define NTOK (BB*LL)   // 4096
#define TCHUNK 32
#define CH 16

typedef unsigned short bf16raw;

static __device__ __forceinline__ bf16raw f2b(float x){
    __nv_bfloat16 h = __float2bfloat16_rn(x);
    return *reinterpret_cast<bf16raw*>(&h);
}
static __device__ __forceinline__ float b2f(bf16raw v){
    __nv_bfloat16 h = *reinterpret_cast<__nv_bfloat16*>(&v);
    return __bfloat162float(h);
}
static __device__ __forceinline__ void cp16(void* dst, const void* src){
    unsigned sa = (unsigned)__cvta_generic_to_shared(dst);
    asm volatile("cp.async.cg.shared.global [%0], [%1], 16;" :: "r"(sa), "l"(src));
}

// ---------------- scratch -------------------------------------------------
__device__ bf16raw g_xz_bf[2][NTOK*2*DI];    // in-proj out (xi|z), bf16
__device__ float   g_xdbl[2][NTOK*64];       // x_proj out fp32 (zeroed; GEMM2 REDs in)
__device__ bf16raw g_xn_bf[NTOK*DM];
__device__ bf16raw g_xi_bf[2][NTOK*DI];      // conv+silu out bf16 (GEMM2 A + scan)
__device__ bf16raw g_ycat_bf[NTOK*2*DI];
__device__ bf16raw g_wcomb[2*DI*DM];         // folded Wcat@Wproj [2048][512]
// bf16 weights
__device__ bf16raw g_w_in[2][DM*2*DI];
__device__ bf16raw g_w_xp[2][DI*64];
__device__ bf16raw g_w_cat[2*DI*DM];
__device__ bf16raw g_w_pj[DM*DM];

// ---------------- fused fp32 -> bf16 conversion ----------------------------
struct CvtArgs { const float* s[9]; bf16raw* d[9]; int off[10]; };

__global__ void cvt_all_kernel(CvtArgs a, int total4){
    int i = blockIdx.x*blockDim.x + threadIdx.x;
    if (i >= total4) return;
    int seg = 0;
    while (i >= a.off[seg+1]) seg++;
    int j = (i - a.off[seg])*4;
    float4 v = *(const float4*)(a.s[seg] + j);
    bf16raw* d = a.d[seg] + j;
    d[0]=f2b(v.x); d[1]=f2b(v.y); d[2]=f2b(v.z); d[3]=f2b(v.w);
}

// ---------------- layernorm: float4 + warp shuffle -------------------------
__global__ __launch_bounds__(128) void ln_kernel(const float* __restrict__ x,
                          const float* __restrict__ g,
                          const float* __restrict__ b) {
    int row = blockIdx.x;
    int tid = threadIdx.x;
    const float4* xr = (const float4*)(x + (long)row*DM);
    float4 v = xr[tid];
    float s = v.x+v.y+v.z+v.w;
    float q = v.x*v.x+v.y*v.y+v.z*v.z+v.w*v.w;
    #pragma unroll
    for (int o=16;o>0;o>>=1){
        s += __shfl_xor_sync(0xffffffffu, s, o);
        q += __shfl_xor_sync(0xffffffffu, q, o);
    }
    __shared__ float ss[4], sq[4];
    int wid = tid>>5, lane = tid&31;
    if (lane==0){ ss[wid]=s; sq[wid]=q; }
    __syncthreads();
    float S = ss[0]+ss[1]+ss[2]+ss[3];
    float Q = sq[0]+sq[1]+sq[2]+sq[3];
    float mu = S*(1.0f/DM);
    float var = Q*(1.0f/DM) - mu*mu;
    float rs = rsqrtf(var + 1e-5f);
    float4 gv = ((const float4*)g)[tid];
    float4 bv = ((const float4*)b)[tid];
    ushort4 o;
    o.x = f2b((v.x-mu)*rs*gv.x + bv.x);
    o.y = f2b((v.y-mu)*rs*gv.y + bv.y);
    o.z = f2b((v.z-mu)*rs*gv.z + bv.z);
    o.w = f2b((v.w-mu)*rs*gv.w + bv.w);
    ((ushort4*)(g_xn_bf + (long)row*DM))[tid] = o;
}

// ---------------- bf16 tensor-core GEMM -------------------------------------
// 128 threads, 2x2 warp grid, warp tile (MT/2)x64, 3-stage cp.async pipeline.
// epi: 0 store fp32 / bf16 Ob; 3 bias+res store; 5 atomicAdd into C.
template<int BK, int MT, int ZS>
__global__ __launch_bounds__(128, 2) void hgemm(
    const bf16raw* __restrict__ Ag, long sA, int lda,
    const bf16raw* __restrict__ Bg, long sB, int ldb,
    float* __restrict__ Cg, long sC, int ldc,
    bf16raw* __restrict__ Obg, long sO,
    int N, int K,
    const float* __restrict__ biasg, long sbias,
    const float* __restrict__ res, int ldres,
    int epi,
    long sA2, long sB2, long sC2)
{
    const int NST = 3;
    int zo, zi;
    if (ZS){ zo = blockIdx.z>>1; zi = blockIdx.z&1; }
    else   { zo = blockIdx.z;    zi = 0; }
    const bf16raw* A = Ag + sA*zo + (ZS ? sA2*zi : 0);
    const bf16raw* B = Bg + sB*zo + (ZS ? sB2*zi : 0);
    float* C   = Cg  ? Cg  + sC*zo + (ZS ? sC2*zi : 0) : nullptr;
    bf16raw* Ob = Obg ? Obg + sO*zo : nullptr;
    const float* bias = biasg ? biasg + sbias*zo : nullptr;

    extern __shared__ __align__(16) bf16raw sdyn[];
    const int ABUF = MT*(BK+8);
    const int BBUF = BK*128;
    bf16raw* As = sdyn;
    bf16raw* Bs = sdyn + NST*ABUF;

    int tid = threadIdx.x;
    int lane = tid & 31, wid = tid >> 5;
    int warp_m = wid & 1, warp_n = wid >> 1;
    int bm = blockIdx.y*MT, bn = blockIdx.x*128;

    const int MTI = MT/32;
    float acc[MTI][8][4];
    #pragma unroll
    for (int a=0;a<MTI;a++) for (int b2=0;b2<8;b2++) for (int c=0;c<4;c++) acc[a][b2][c]=0.f;

    int KT = K / BK;
    const int CPR = BK/8;

    auto loadTile = [&](int kt, int buf){
        int k0 = kt*BK;
        #pragma unroll
        for (int i=0;i<MT*BK/1024;i++){
            int q = tid + i*128;
            int r = q / CPR, c = q % CPR;
            const bf16raw* src = A + (long)(bm+r)*lda + k0 + c*8;
            unsigned sa = (unsigned)__cvta_generic_to_shared(&As[buf*ABUF + r*(BK+8) + c*8]);
            asm volatile("cp.async.cg.shared.global [%0], [%1], 16;\n" :: "r"(sa), "l"(src));
        }
        #pragma unroll
        for (int i=0;i<BK/8;i++){
            int q = tid + i*128;
            int r = q>>4, c = q&15;
            int gcol = bn + c*8;
            const bf16raw* src = B + (long)(k0+r)*ldb + gcol;
            unsigned sa = (unsigned)__cvta_generic_to_shared(&Bs[buf*BBUF + r*128 + ((c ^ (r&7))*8)]);
            int sz = (gcol < N) ? 16 : 0;
            asm volatile("cp.async.cg.shared.global [%0], [%1], 16, %2;\n" :: "r"(sa), "l"(src), "r"(sz));
        }
    };

    #pragma unroll
    for (int p=0; p<NST-1; p++){
        loadTile(p, p);
        asm volatile("cp.async.commit_group;\n" ::: "memory");
    }

    for (int kt=0; kt<KT; kt++){
        asm volatile("cp.async.wait_group %0;\n" :: "n"(NST-2) : "memory");
        __syncthreads();
        int buf = kt % NST;

        #pragma unroll
        for (int ks=0; ks<BK/16; ks++){
            unsigned af[MTI][4];
            #pragma unroll
            for (int mt=0; mt<MTI; mt++){
                int row = warp_m*(MT/2) + mt*16 + (lane&15);
                int chunk = ks*2 + (lane>>4);
                unsigned addr = (unsigned)__cvta_generic_to_shared(&As[buf*ABUF + row*(BK+8) + chunk*8]);
                asm volatile("ldmatrix.sync.aligned.m8n8.x4.shared.b16 {%0,%1,%2,%3}, [%4];"
                    : "=r"(af[mt][0]),"=r"(af[mt][1]),"=r"(af[mt][2]),"=r"(af[mt][3]) : "r"(addr));
            }
            unsigned bfm[8][2];
            #pragma unroll
            for (int jn=0; jn<4; jn++){
                int row = ks*16 + (lane&15);
                int c = warp_n*8 + jn*2 + (lane>>4);
                unsigned addr = (unsigned)__cvta_generic_to_shared(&Bs[buf*BBUF + row*128 + ((c ^ (row&7))*8)]);
                unsigned r0,r1,r2,r3;
                asm volatile("ldmatrix.sync.aligned.m8n8.x4.trans.shared.b16 {%0,%1,%2,%3}, [%4];"
                    : "=r"(r0),"=r"(r1),"=r"(r2),"=r"(r3) : "r"(addr));
                bfm[jn*2][0]=r0;   bfm[jn*2][1]=r1;
                bfm[jn*2+1][0]=r2; bfm[jn*2+1][1]=r3;
            }
            #pragma unroll
            for (int mt=0; mt<MTI; mt++)
                #pragma unroll
                for (int nt=0; nt<8; nt++){
                    asm volatile("mma.sync.aligned.m16n8k16.row.col.f32.bf16.bf16.f32 "
                        "{%0,%1,%2,%3}, {%4,%5,%6,%7}, {%8,%9}, {%0,%1,%2,%3};"
                        : "+f"(acc[mt][nt][0]),"+f"(acc[mt][nt][1]),
                          "+f"(acc[mt][nt][2]),"+f"(acc[mt][nt][3])
                        : "r"(af[mt][0]),"r"(af[mt][1]),"r"(af[mt][2]),"r"(af[mt][3]),
                          "r"(bfm[nt][0]),"r"(bfm[nt][1]));
                }
        }

        int nl = kt + NST - 1;
        if (nl < KT){
            loadTile(nl, nl % NST);
            asm volatile("cp.async.commit_group;\n" ::: "memory");
        } else {
            asm volatile("cp.async.commit_group;\n" ::: "memory");
        }
    }

    #pragma unroll
    for (int mt=0; mt<MTI; mt++){
        #pragma unroll
        for (int i2=0; i2<2; i2++){
            long r = bm + warp_m*(MT/2) + mt*16 + (lane>>2) + i2*8;
            #pragma unroll
            for (int nt=0; nt<8; nt++){
                int cbase = bn + warp_n*64 + nt*8 + (lane&3)*2;
                #pragma unroll
                for (int j=0; j<2; j++){
                    int c = cbase + j;
                    if (c >= N) continue;
                    float v = acc[mt][nt][i2*2+j];
                    if (epi==5){ atomicAdd(&C[r*ldc + c], v); continue; }
                    if (epi==3){ v += bias[c] + res[r*ldres + c]; }
                    if (C)  C[r*ldc + c] = v;
                    if (Ob) Ob[r*ldc + c] = f2b(v);
                }
            }
        }
    }
}

// ---------------- depthwise conv + SiLU: sliding window, 4 t-outputs/thread -
__global__ __launch_bounds__(256) void conv_kernel(
    const float* __restrict__ wf, const float* __restrict__ biasf,
    const float* __restrict__ wb, const float* __restrict__ biasb)
{
    int dir = blockIdx.z;
    const float* w    = dir ? wb : wf;
    const float* bias = dir ? biasb : biasf;
    int q = blockIdx.x*blockDim.x + threadIdx.x;   // over NTOK*DI/4
    int d    = q & (DI-1);
    int tblk = (q >> 10) & (LL/4 - 1);
    int b    = q >> 19;
    int t0   = tblk*4;
    const bf16raw* xz = g_xz_bf[dir];

    float w0=w[d*4+0], w1=w[d*4+1], w2=w[d*4+2], w3=w[d*4+3];
    float bv = bias[d];

    float v[7];
    #pragma unroll
    for (int i=0;i<7;i++){
        int tt = (dir==0) ? (t0 - 3 + i) : (t0 + i);
        v[i] = (tt >= 0 && tt < LL)
             ? b2f(xz[((long)(b*LL + tt)*2*DI) + d]) : 0.f;
    }

    bf16raw out[4];
    #pragma unroll
    for (int s=0;s<4;s++){
        float acc;
        if (dir==0)
            acc = fmaf(w0, v[s], fmaf(w1, v[s+1], fmaf(w2, v[s+2], fmaf(w3, v[s+3], bv))));
        else
            acc = fmaf(w0, v[s+3], fmaf(w1, v[s+2], fmaf(w2, v[s+1], fmaf(w3, v[s], bv))));
        out[s] = f2b(acc / (1.f + __expf(-acc)));
    }
    #pragma unroll
    for (int s=0;s<4;s++)
        g_xi_bf[dir][((long)(b*LL + t0 + s))*DI + d] = out[s];
}

// ---------------- selective scan + fused dt projection ---------------------
struct ScanSmem {
    float   xd[2][TCHUNK][64];   // xdbl row: [0:32) dt-in, [32:48) B, [48:64) C
    bf16raw xi[2][TCHUNK][CH];
    bf16raw z [2][TCHUNK][CH];
    float   dtw[32][CH];
    float   dts[TCHUNK][CH];
    float   dtx[TCHUNK][CH];
    float   dtb[CH];
    float   p [TCHUNK][CH][17];
};

__global__ __launch_bounds__(256) void scan_kernel(
    const float* __restrict__ fA, const float* __restrict__ fD,
    const float* __restrict__ bA, const float* __restrict__ bD,
    const float* __restrict__ fdtw, const float* __restrict__ fdtb,
    const float* __restrict__ bdtw, const float* __restrict__ bdtb)
{
    extern __shared__ char smem_raw[];
    ScanSmem* S = reinterpret_cast<ScanSmem*>(smem_raw);

    int dir = blockIdx.z;
    int b   = blockIdx.y;
    int d0  = blockIdx.x * CH;
    const float* A_log = dir ? bA : fA;
    const float* Dp    = dir ? bD : fD;
    const float* dtwg  = dir ? bdtw : fdtw;
    const float* dtbg  = dir ? bdtb : fdtb;

    int tid  = threadIdx.x;
    int wid  = tid >> 5, lane = tid & 31;
    int half = lane >> 4, n = lane & 15;
    int dl   = wid*2 + half;

    float a    = -expf(A_log[(d0+dl)*DS + n]);
    float Dv_r = Dp[d0 + (tid & 15)];

    #pragma unroll
    for (int i=0;i<2;i++){
        int q = tid + i*256;
        S->dtw[q>>4][q&15] = dtwg[(long)(q>>4)*DI + d0 + (q&15)];
    }
    if (tid < CH) S->dtb[tid] = dtbg[d0 + tid];

    const bf16raw* xip = g_xi_bf[dir];
    const bf16raw* xzp = g_xz_bf[dir];
    const float*   bcp = g_xdbl[dir];

    const int NCH = LL / TCHUNK;

    auto loadChunk = [&](int c, int buf){
        {
            #pragma unroll
            for (int i=0;i<2;i++){
                int q = tid + i*256;
                int row = q >> 4, seg = q & 15;
                int trow = (dir==0) ? c*TCHUNK+row : (LL-1) - (c*TCHUNK+row);
                long tok = (long)b*LL + trow;
                cp16(&S->xd[buf][row][seg*4], bcp + tok*64 + seg*4);
            }
        }
        if (tid < 64){
            int row = tid >> 1, seg = tid & 1;
            int trow = (dir==0) ? c*TCHUNK+row : (LL-1) - (c*TCHUNK+row);
            long tok = (long)b*LL + trow;
            cp16(&S->xi[buf][row][seg*8], xip + tok*DI + d0 + seg*8);
        } else if (tid < 128){
            int rem = tid - 64;
            int row = rem >> 1, seg = rem & 1;
            int trow = (dir==0) ? c*TCHUNK+row : (LL-1) - (c*TCHUNK+row);
            long tok = (long)b*LL + trow;
            cp16(&S->z[buf][row][seg*8], xzp + tok*2*DI + DI + d0 + seg*8);
        }
    };

    float h = 0.f;
    loadChunk(0, 0);
    asm volatile("cp.async.commit_group;\n" ::: "memory");

    for (int c=0; c<NCH; c++){
        if (c+1 < NCH) loadChunk(c+1, (c+1)&1);
        asm volatile("cp.async.commit_group;\n" ::: "memory");
        asm volatile("cp.async.wait_group 1;\n" ::: "memory");
        __syncthreads();
        int buf = c & 1;

        // ---- pre-phase: dt projection + dtx = dt*xi ----
        #pragma unroll
        for (int rep=0; rep<2; rep++){
            int o = tid + rep*256;
            int s = o >> 4, dlo = o & 15;
            float acc = S->dtb[dlo];
            #pragma unroll
            for (int k=0;k<32;k++) acc = fmaf(S->xd[buf][s][k], S->dtw[k][dlo], acc);
            float dtv = (acc > 20.f) ? acc : __logf(1.f + __expf(acc));
            S->dts[s][dlo] = dtv;
            S->dtx[s][dlo] = dtv * b2f(S->xi[buf][s][dlo]);
        }
        __syncthreads();

        // ---- serial recurrence ----
        #pragma unroll
        for (int s=0; s<TCHUNK; s++){
            float dtv = S->dts[s][dl];
            float dtx = S->dtx[s][dl];
            float Bt  = S->xd[buf][s][32+n];
            float Ct  = S->xd[buf][s][48+n];
            float dA  = __expf(dtv * a);
            h = fmaf(dA, h, dtx*Bt);
            S->p[s][dl][n] = h * Ct;
        }
        __syncthreads();

        // ---- reduction + epilogue + store ----
        #pragma unroll
        for (int rep=0; rep<2; rep++){
            int o  = tid + rep*256;
            int s  = o >> 4, dlo = o & 15;
            float sum = 0.f;
            #pragma unroll
            for (int k=0;k<16;k++) sum += S->p[s][dlo][k];
            float xiv = b2f(S->xi[buf][s][dlo]);
            float zv  = b2f(S->z[buf][s][dlo]);
            float yv  = (sum + xiv*Dv_r) * zv / (1.f + __expf(-zv));
            int trow  = (dir==0) ? c*TCHUNK+s : (LL-1) - (c*TCHUNK+s);
            g_ycat_bf[((long)b*LL + trow)*2*DI + dir*DI + d0 + dlo] = f2b(yv);
        }
        __syncthreads();
    }
}

// ---------------- host launcher --------------------------------------------
extern "C" void kernel_launch(void* const* d_in, const int* in_sizes, int n_in,
                              void* d_out, int out_size){
    const float* x      = (const float*)d_in[0];
    const float* ln_g   = (const float*)d_in[1];
    const float* ln_b   = (const float*)d_in[2];
    const float* proj_w = (const float*)d_in[3];
    const float* proj_b = (const float*)d_in[4];
    const float* P[2][9];
    for (int dir=0; dir<2; dir++)
        for (int i=0;i<9;i++)
            P[dir][i] = (const float*)d_in[5 + dir*9 + i];

    float   *p_xdbl;
    bf16raw *p_xzb,*p_xn,*p_xib,*p_ycat,*p_wcomb;
    bf16raw *w_in,*w_xp,*w_cat,*w_pj;
    cudaGetSymbolAddress((void**)&p_xzb,   g_xz_bf);
    cudaGetSymbolAddress((void**)&p_xdbl,  g_xdbl);
    cudaGetSymbolAddress((void**)&p_xn,    g_xn_bf);
    cudaGetSymbolAddress((void**)&p_xib,   g_xi_bf);
    cudaGetSymbolAddress((void**)&p_ycat,  g_ycat_bf);
    cudaGetSymbolAddress((void**)&p_wcomb, g_wcomb);
    cudaGetSymbolAddress((void**)&w_in,    g_w_in);
    cudaGetSymbolAddress((void**)&w_xp,    g_w_xp);
    cudaGetSymbolAddress((void**)&w_cat,   g_w_cat);
    cudaGetSymbolAddress((void**)&w_pj,    g_w_pj);

    const int SMEM_128 = 3*(128*72 + 64*128)*2;   // 104448
    const int SMEM_64  = 3*(64*72  + 64*128)*2;   // 76800
    cudaFuncSetAttribute((hgemm<64,128,0>), cudaFuncAttributeMaxDynamicSharedMemorySize, SMEM_128);
    cudaFuncSetAttribute((hgemm<64,64,0>),  cudaFuncAttributeMaxDynamicSharedMemorySize, SMEM_64);
    cudaFuncSetAttribute((hgemm<64,64,1>),  cudaFuncAttributeMaxDynamicSharedMemorySize, SMEM_64);

    // 0a. zero xdbl accumulator (GEMM2 REDs into it)
    cudaMemsetAsync(p_xdbl, 0, (size_t)2*NTOK*64*sizeof(float));

    // 0b. fused weight conversion (dt_w stays fp32 for the fused scan)
    {
        CvtArgs a;
        const float* srcs[7] = {P[0][0], P[1][0], P[0][3], P[1][3],
                                P[0][8], P[1][8], proj_w};
        bf16raw* dsts[7] = {w_in, w_in+DM*2*DI, w_xp, w_xp+DI*64,
                            w_cat, w_cat+DI*DM, w_pj};
        int sizes[7] = {DM*2*DI, DM*2*DI, DI*64, DI*64, DI*DM, DI*DM, DM*DM};
        int acc = 0;
        for (int i=0;i<7;i++){ a.s[i]=srcs[i]; a.d[i]=dsts[i]; a.off[i]=acc; acc += sizes[i]/4; }
        for (int i=7;i<10;i++) a.off[i] = acc;
        cvt_all_kernel<<<(acc+255)/256, 256>>>(a, acc);
    }

    // 0c. fold: Wcomb = [f_out_w; b_out_w] @ proj_w   (2048 x 512, K=512)
    hgemm<64,64,0><<<dim3(DM/128, 2*DI/64, 1), 128, SMEM_64>>>(
        w_cat, 0, DM,
        w_pj,  0, DM,
        nullptr, 0, DM,
        p_wcomb, 0,
        DM, DM, nullptr, 0, nullptr, 0, 0, 0,0,0);

    // 1. layernorm -> bf16
    ln_kernel<<<NTOK, 128>>>(x, ln_g, ln_b);

    // 2. in-proj: xz = xn @ in_w  (4096 x 2048, K=512) -> bf16
    hgemm<64,128,0><<<dim3(2*DI/128, NTOK/128, 2), 128, SMEM_128>>>(
        p_xn, 0, DM,
        w_in, (long)DM*2*DI, 2*DI,
        nullptr, 0, 2*DI,
        p_xzb, (long)NTOK*2*DI,
        2*DI, DM, nullptr, 0, nullptr, 0, 0, 0,0,0);

    // 3. conv + SiLU (sliding-window, 4 outputs/thread)
    conv_kernel<<<dim3(NTOK*DI/4/256,1,2), 256>>>(P[0][1], P[0][2], P[1][1], P[1][2]);

    // 4. x_proj split-K x2, atomic-add epilogue into xdbl (256 CTAs)
    hgemm<64,64,1><<<dim3(1, NTOK/64, 4), 128, SMEM_64>>>(
        p_xib, (long)NTOK*DI, DI,
        w_xp,  (long)DI*64,   64,
        p_xdbl, (long)NTOK*64, 64,
        nullptr, 0,
        64, 512, nullptr, 0, nullptr, 0, 5,
        /*sA2=*/512, /*sB2=*/(long)512*64, /*sC2=*/0);

    // 5+6. selective scan with fused dt projection -> ycat bf16
    cudaFuncSetAttribute(scan_kernel, cudaFuncAttributeMaxDynamicSharedMemorySize,
                         (int)sizeof(ScanSmem));
    scan_kernel<<<dim3(DI/CH, BB, 2), 256, sizeof(ScanSmem)>>>(
        P[0][6], P[0][7], P[1][6], P[1][7],
        P[0][4], P[0][5], P[1][4], P[1][5]);

    // 7. out = ycat @ Wcomb + proj_b + x  (4096 x 512, K=2048), 256 CTAs
    hgemm<64,64,0><<<dim3(DM/128, NTOK/64, 1), 128, SMEM_64>>>(
        p_ycat, 0, 2*DI,
        p_wcomb, 0, DM,
        (float*)d_out, 0, DM,
        nullptr, 0,
        DM, 2*DI, proj_b, 0, x, DM, 3, 0,0,0);
}